// round 12
// baseline (speedup 1.0000x reference)
#include <cuda_runtime.h>

// ============================================================================
// Layer_70411693850653 — equivariant GNN layer, fully fused. (R10 + prefetch)
//
//  * messages[384:640] never consumed -> skipped
//  * agg == 1.5 * feats[:, :128] -> skip connection folded into weights
//  * scatter_mean via bucketed inverse-CSR + register gather (no float atomics)
//  * quad-packed smem weights (LDS.128); pair-split u-reduction in Phase B
//  * R11: dependency-free prefetch of next tile's {deg, bucket} (unconditional
//    per-lane bucket load, guarded only at consume) hidden under Phase B
//  * R11: dedicated exchange buffer sX -> one fewer barrier per tile
//  * TILE=8, 41KB smem, 5 blocks/SM
// ============================================================================

#define N_MAX 50000
#define CAP   32
#define TILE  8
#define FS    384
#define NBLK  740         // 5 per SM on 148 SMs

__device__ int  g_deg[N_MAX];            // zero-init at load; k_main resets
__device__ int2 g_bucket[N_MAX * CAP];   // {sender, edge}

// ---------------------------------------------------------------------------
__global__ void k_fill(const int* __restrict__ recv,
                       const int* __restrict__ senders, int E) {
    int e = blockIdx.x * blockDim.x + threadIdx.x;
    if (e < E) {
        int r = recv[e];
        int slot = atomicAdd(&g_deg[r], 1);
        if (slot < CAP) g_bucket[r * CAP + slot] = make_int2(senders[e], e);
    }
}

// ---------------------------------------------------------------------------
__global__ void __launch_bounds__(256, 5) k_main(
    const float* __restrict__ nf, const float* __restrict__ sh,
    const float* __restrict__ W0, const float* __restrict__ W1,
    const float* __restrict__ Ws0, const float* __restrict__ Ws1,
    float* __restrict__ out, int N)
{
    // weights as u-quads: sWq[q*32 + lane] = {W[4q][lane], .., W[4q+3][lane]}
    __shared__ __align__(16) float4 sW0q[24 * 32];
    __shared__ __align__(16) float4 sW1q[24 * 32];
    __shared__ __align__(16) float  sF[TILE * FS];
    __shared__ __align__(16) float  sX[4 * 8 * 32];   // pair partial sums

    const float invA = 0.10206207261596575f;         // 1/sqrt(96)
    const float cB   = 1.5f * 0.17677669529663687f;  // 1.5/sqrt(32)
    const float INV_SQRT3 = 0.5773502691896258f;

    const int t    = threadIdx.x;
    const int w    = t >> 5;
    const int lane = t & 31;

    // Effective weights (skip folded), packed into quads
    for (int i = t; i < 24 * 32; i += 256) {
        int q = i >> 5, l = i & 31;
        float4 a, b;
        float* pa = &a.x; float* pb = &b.x;
        #pragma unroll
        for (int k = 0; k < 4; k++) {
            int u = 4 * q + k;
            float w0 = W0[u * 32 + l] * invA;
            float w1 = W1[u * 32 + l] * invA;
            if (u < 32) { w0 = fmaf(cB, Ws0[u * 32 + l], w0);
                          w1 = fmaf(cB, Ws1[u * 32 + l], w1); }
            pa[k] = w0; pb[k] = w1;
        }
        sW0q[i] = a;
        sW1q[i] = b;
    }

    // Phase B role (loop-invariant): pair owns one row-type over 8 nodes,
    // halves split the u-range.
    const int pair = w >> 1;          // 0=scalar, 1..3 = vector comp pair-1
    const int h    = w & 1;           // 0: u in [0,48), 1: u in [48,96)
    const float4* Wq  = (pair == 0) ? sW0q : sW1q;
    const int     cc  = pair - 1;
    const int     offA = (pair == 0) ? 0   : 32 + 32 * cc;
    const int     offB = (pair == 0) ? 128 : 192 + 64 * cc;

    const int ntiles = (N + TILE - 1) / TILE;

    // ---- dependency-free prefetch of first tile's {deg, bucket} ----------
    int  pf_d  = 0;
    int2 pf_se = make_int2(0, 0);
    {
        int n = blockIdx.x * TILE + w;
        if (n < N) {
            pf_d  = g_deg[n];
            if (lane == 0) g_deg[n] = 0;            // maintain zero-invariant
            pf_se = g_bucket[n * CAP + lane];       // unconditional (CAP==32)
        }
    }

    for (int tile = blockIdx.x; tile < ntiles; tile += gridDim.x) {
        __syncthreads();   // protects sF and sX against previous tile readers

        // ---------------- Phase A: warp w owns node tile*8 + w -------------
        {
            const int d  = pf_d;
            const int dc = min(d, CAP);
            const int my_s = pf_se.x;

            float4 my_sh = make_float4(0.f, 0.f, 0.f, 0.f);
            if (lane < dc)    // only dependent link left inline
                my_sh = *reinterpret_cast<const float4*>(sh + (size_t)pf_se.y * 4);

            float a0 = 0.f, ax = 0.f, ay = 0.f, az = 0.f;
            float p00 = 0.f, dot = 0.f;
            float qx = 0.f, qy = 0.f, qz = 0.f;   // p01 = s0*f1
            float rx = 0.f, ry = 0.f, rz = 0.f;   // p10 = f0*s1

            for (int j = 0; j < dc; j++) {
                int   s   = __shfl_sync(0xffffffffu, my_s,    j);
                float s0  = __shfl_sync(0xffffffffu, my_sh.x, j);
                float s1x = __shfl_sync(0xffffffffu, my_sh.y, j);
                float s1y = __shfl_sync(0xffffffffu, my_sh.z, j);
                float s1z = __shfl_sync(0xffffffffu, my_sh.w, j);

                const float* row = nf + (size_t)s * 128;
                float f0 = row[lane];
                float g0 = row[32 + 3 * lane];
                float g1 = row[33 + 3 * lane];
                float g2 = row[34 + 3 * lane];

                a0 += f0; ax += g0; ay += g1; az += g2;
                p00 = fmaf(s0, f0, p00);
                dot = fmaf(s1x, g0, fmaf(s1y, g1, fmaf(s1z, g2, dot)));
                qx  = fmaf(s0, g0, qx);
                qy  = fmaf(s0, g1, qy);
                qz  = fmaf(s0, g2, qz);
                rx  = fmaf(f0, s1x, rx);
                ry  = fmaf(f0, s1y, ry);
                rz  = fmaf(f0, s1z, rz);
            }

            const float scale = 1.0f / (1.5f * (float)max(d, 1));
            float* F = sF + w * FS;
            F[        lane] = a0 * scale;
            F[ 32   + lane] = ax * scale;
            F[ 64   + lane] = ay * scale;
            F[ 96   + lane] = az * scale;
            F[128   + lane] = p00 * scale;
            F[160   + lane] = dot * scale * INV_SQRT3;
            F[192   + lane] = qx * scale;   // c=0: p01
            F[224   + lane] = rx * scale;   // c=0: p10
            F[256   + lane] = qy * scale;   // c=1
            F[288   + lane] = ry * scale;
            F[320   + lane] = qz * scale;   // c=2
            F[352   + lane] = rz * scale;
        }

        // ---- prefetch NEXT tile (independent loads, no consumers here) ----
        {
            pf_d = 0;
            int nn = (tile + gridDim.x) * TILE + w;
            if (tile + gridDim.x < ntiles && nn < N) {
                pf_d  = g_deg[nn];
                if (lane == 0) g_deg[nn] = 0;
                pf_se = g_bucket[nn * CAP + lane];
            }
        }
        __syncthreads();   // sF ready for Phase B

        // ---------------- Phase B: pair computes 8 rows, halves split u ----
        float acc[8];
        #pragma unroll
        for (int r = 0; r < 8; r++) acc[r] = 0.f;

        if (h == 0) {
            #pragma unroll
            for (int q = 0; q < 8; q++) {            // u in [0,32)  (A region)
                float4 wv = Wq[q * 32 + lane];
                #pragma unroll
                for (int r = 0; r < 8; r++) {
                    float4 a = *reinterpret_cast<const float4*>(
                        sF + r * FS + offA + 4 * q);
                    acc[r] = fmaf(a.x, wv.x, fmaf(a.y, wv.y,
                             fmaf(a.z, wv.z, fmaf(a.w, wv.w, acc[r]))));
                }
            }
            #pragma unroll
            for (int q = 0; q < 4; q++) {            // u in [32,48) (B region)
                float4 wv = Wq[(8 + q) * 32 + lane];
                #pragma unroll
                for (int r = 0; r < 8; r++) {
                    float4 a = *reinterpret_cast<const float4*>(
                        sF + r * FS + offB + 4 * q);
                    acc[r] = fmaf(a.x, wv.x, fmaf(a.y, wv.y,
                             fmaf(a.z, wv.z, fmaf(a.w, wv.w, acc[r]))));
                }
            }
        } else {
            #pragma unroll
            for (int q = 4; q < 16; q++) {           // u in [48,96) (B region)
                float4 wv = Wq[(8 + q) * 32 + lane];
                #pragma unroll
                for (int r = 0; r < 8; r++) {
                    float4 a = *reinterpret_cast<const float4*>(
                        sF + r * FS + offB + 4 * q);
                    acc[r] = fmaf(a.x, wv.x, fmaf(a.y, wv.y,
                             fmaf(a.z, wv.z, fmaf(a.w, wv.w, acc[r]))));
                }
            }
            // park partials immediately (sX protected by top-of-loop barrier)
            #pragma unroll
            for (int r = 0; r < 8; r++)
                sX[(pair * 8 + r) * 32 + lane] = acc[r];
        }
        __syncthreads();   // h1 partials visible

        // h=0 combines and stores
        if (h == 0) {
            #pragma unroll
            for (int r = 0; r < 8; r++) {
                int n = tile * TILE + r;
                if (n < N) {
                    float res = acc[r] + sX[(pair * 8 + r) * 32 + lane];
                    if (pair == 0) out[(size_t)n * 128 + lane] = res;
                    else           out[(size_t)n * 128 + 32 + 3 * lane + cc] = res;
                }
            }
        }
    }
}

// ---------------------------------------------------------------------------
extern "C" void kernel_launch(void* const* d_in, const int* in_sizes, int n_in,
                              void* d_out, int out_size)
{
    const float* nf       = (const float*)d_in[0];
    const float* sh       = (const float*)d_in[1];
    const int*   senders  = (const int*)  d_in[2];
    const int*   recv     = (const int*)  d_in[3];
    const float* W0       = (const float*)d_in[4];
    const float* W1       = (const float*)d_in[5];
    const float* Ws0      = (const float*)d_in[6];
    const float* Ws1      = (const float*)d_in[7];
    float* out = (float*)d_out;

    int N = in_sizes[0] / 128;
    int E = in_sizes[2];

    k_fill<<<(E + 511) / 512, 512>>>(recv, senders, E);
    k_main<<<NBLK, 256>>>(nf, sh, W0, W1, Ws0, Ws1, out, N);
}

// round 13
// speedup vs baseline: 2.8769x; 2.8769x over previous
#include <cuda_runtime.h>
#include <cstdint>

// ============================================================================
// Layer_70411693850653 — equivariant GNN layer. (R10 gather + tf32 MMA epilogue)
//
//  * messages[384:640] never consumed -> skipped
//  * agg == 1.5 * feats[:, :128] -> skip connection folded into weights
//  * scatter_mean via bucketed inverse-CSR + register gather (no float atomics)
//  * R13: Phase B = tensor-core GEMM (mma.sync.m16n8k8.tf32):
//      sF row-major [48 x 100] (8 scalar rows + 8 pad + 24 vector rows + 8 pad)
//      weights transposed Wt[v][u], tf32-rounded (cvt.rna) once in prologue
//      6 warps = (Mtile 0..2) x (n-half); pad rows' outputs never stored
//  * NO cross-barrier prefetch (twice-measured regression)
//  * TILE=8, 44.8KB smem, 5 blocks/SM
// ============================================================================

#define N_MAX 50000
#define CAP   32
#define TILE  8
#define FSP   100        // row stride (words): banks (4*r0+c0)%32 = permutation
#define NROW  48
#define NBLK  740        // 5 per SM on 148 SMs

__device__ int  g_deg[N_MAX];            // zero-init at load; k_main resets
__device__ int2 g_bucket[N_MAX * CAP];   // {sender, edge}

// ---------------------------------------------------------------------------
__global__ void k_fill(const int* __restrict__ recv,
                       const int* __restrict__ senders, int E) {
    int e = blockIdx.x * blockDim.x + threadIdx.x;
    if (e < E) {
        int r = recv[e];
        int slot = atomicAdd(&g_deg[r], 1);
        if (slot < CAP) g_bucket[r * CAP + slot] = make_int2(senders[e], e);
    }
}

// ---------------------------------------------------------------------------
__device__ __forceinline__ uint32_t f2tf(float x) {
    uint32_t r;
    asm("cvt.rna.tf32.f32 %0, %1;" : "=r"(r) : "f"(x));
    return r;
}

__device__ __forceinline__ void mma_tf32(float c[4],
    uint32_t a0, uint32_t a1, uint32_t a2, uint32_t a3,
    uint32_t b0, uint32_t b1)
{
    asm volatile(
        "mma.sync.aligned.m16n8k8.row.col.f32.tf32.tf32.f32 "
        "{%0,%1,%2,%3}, {%4,%5,%6,%7}, {%8,%9}, {%0,%1,%2,%3};"
        : "+f"(c[0]), "+f"(c[1]), "+f"(c[2]), "+f"(c[3])
        : "r"(a0), "r"(a1), "r"(a2), "r"(a3), "r"(b0), "r"(b1));
}

// ---------------------------------------------------------------------------
__global__ void __launch_bounds__(256, 5) k_main(
    const float* __restrict__ nf, const float* __restrict__ sh,
    const float* __restrict__ W0, const float* __restrict__ W1,
    const float* __restrict__ Ws0, const float* __restrict__ Ws1,
    float* __restrict__ out, int N)
{
    __shared__ uint32_t sF [NROW * FSP];     // tf32 feats rows   (19.2 KB)
    __shared__ uint32_t sW0[32 * FSP];       // Wt0[v][u] tf32    (12.8 KB)
    __shared__ uint32_t sW1[32 * FSP];       // Wt1[v][u] tf32    (12.8 KB)

    const float invA = 0.10206207261596575f;         // 1/sqrt(96)
    const float cB   = 1.5f * 0.17677669529663687f;  // 1.5/sqrt(32)
    const float INV_SQRT3 = 0.5773502691896258f;

    const int t    = threadIdx.x;
    const int w    = t >> 5;
    const int lane = t & 31;

    // ---- prologue: effective weights, transposed to [v][u], tf32 ----------
    for (int i = t; i < 96 * 32; i += 256) {
        int u = i >> 5, v = i & 31;
        float w0 = W0[i] * invA;
        float w1 = W1[i] * invA;
        if (u < 32) { w0 = fmaf(cB, Ws0[i], w0); w1 = fmaf(cB, Ws1[i], w1); }
        sW0[v * FSP + u] = f2tf(w0);
        sW1[v * FSP + u] = f2tf(w1);
    }
    // zero the pad rows (8-15, 40-47) once; their C rows are never stored,
    // but keep them clean anyway
    for (int i = t; i < 8 * FSP; i += 256) {
        sF[(8  + i / FSP) * FSP + (i % FSP)] = 0;
        sF[(40 + i / FSP) * FSP + (i % FSP)] = 0;
    }

    // fragment indices (loop-invariant)
    const int r0 = lane >> 2;   // 0..7
    const int c0 = lane & 3;    // 0..3
    // Phase B role: warps 0..5 = (Mtile m, n-half nh); warps 6,7 idle in B
    const int m  = w >> 1;                  // 0,1,2 for w<6
    const int nh = w & 1;
    const int mbase = m * 16;
    const int nbase = nh * 16;
    const uint32_t* Wt = (m == 0) ? sW0 : sW1;

    const int ntiles = (N + TILE - 1) / TILE;
    for (int tile = blockIdx.x; tile < ntiles; tile += gridDim.x) {
        __syncthreads();   // previous tile's Phase B readers done with sF

        // ---------------- Phase A: warp w owns node tile*8 + w -------------
        {
            const int n = tile * TILE + w;

            float a0 = 0.f, ax = 0.f, ay = 0.f, az = 0.f;
            float p00 = 0.f, dot = 0.f;
            float qx = 0.f, qy = 0.f, qz = 0.f;   // p01 = s0*f1
            float rx = 0.f, ry = 0.f, rz = 0.f;   // p10 = f0*s1

            int d = 0;
            if (n < N) d = g_deg[n];
            const int dc = min(d, CAP);
            if (n < N && lane == 0) g_deg[n] = 0;   // maintain zero-invariant

            int    my_s  = 0;
            float4 my_sh = make_float4(0.f, 0.f, 0.f, 0.f);
            if (lane < dc) {
                int2 se = g_bucket[n * CAP + lane];
                my_s    = se.x;
                my_sh   = *reinterpret_cast<const float4*>(sh + (size_t)se.y * 4);
            }

            for (int j = 0; j < dc; j++) {
                int   s   = __shfl_sync(0xffffffffu, my_s,    j);
                float s0  = __shfl_sync(0xffffffffu, my_sh.x, j);
                float s1x = __shfl_sync(0xffffffffu, my_sh.y, j);
                float s1y = __shfl_sync(0xffffffffu, my_sh.z, j);
                float s1z = __shfl_sync(0xffffffffu, my_sh.w, j);

                const float* row = nf + (size_t)s * 128;
                float f0 = row[lane];
                float g0 = row[32 + 3 * lane];
                float g1 = row[33 + 3 * lane];
                float g2 = row[34 + 3 * lane];

                a0 += f0; ax += g0; ay += g1; az += g2;
                p00 = fmaf(s0, f0, p00);
                dot = fmaf(s1x, g0, fmaf(s1y, g1, fmaf(s1z, g2, dot)));
                qx  = fmaf(s0, g0, qx);
                qy  = fmaf(s0, g1, qy);
                qz  = fmaf(s0, g2, qz);
                rx  = fmaf(f0, s1x, rx);
                ry  = fmaf(f0, s1y, ry);
                rz  = fmaf(f0, s1z, rz);
            }

            const float scale = 1.0f / (1.5f * (float)max(d, 1));
            // scalar row w:            [a0, p00, dot]
            sF[ w       * FSP +      lane] = f2tf(a0 * scale);
            sF[ w       * FSP + 32 + lane] = f2tf(p00 * scale);
            sF[ w       * FSP + 64 + lane] = f2tf(dot * scale * INV_SQRT3);
            // x row 16+w:              [ax, qx, rx]
            sF[(16 + w) * FSP +      lane] = f2tf(ax * scale);
            sF[(16 + w) * FSP + 32 + lane] = f2tf(qx * scale);
            sF[(16 + w) * FSP + 64 + lane] = f2tf(rx * scale);
            // y row 24+w:              [ay, qy, ry]
            sF[(24 + w) * FSP +      lane] = f2tf(ay * scale);
            sF[(24 + w) * FSP + 32 + lane] = f2tf(qy * scale);
            sF[(24 + w) * FSP + 64 + lane] = f2tf(ry * scale);
            // z row 32+w:              [az, qz, rz]
            sF[(32 + w) * FSP +      lane] = f2tf(az * scale);
            sF[(32 + w) * FSP + 32 + lane] = f2tf(qz * scale);
            sF[(32 + w) * FSP + 64 + lane] = f2tf(rz * scale);
        }
        __syncthreads();   // sF ready

        // ---------------- Phase B: tf32 MMA, warps 0..5 --------------------
        if (w < 6) {
            float c[2][4];
            #pragma unroll
            for (int nt = 0; nt < 2; nt++)
                #pragma unroll
                for (int i = 0; i < 4; i++) c[nt][i] = 0.f;

            #pragma unroll
            for (int k = 0; k < 12; k++) {
                const int kb = 8 * k;
                uint32_t a0 = sF[(mbase + r0)     * FSP + kb + c0];
                uint32_t a1 = sF[(mbase + r0 + 8) * FSP + kb + c0];
                uint32_t a2 = sF[(mbase + r0)     * FSP + kb + c0 + 4];
                uint32_t a3 = sF[(mbase + r0 + 8) * FSP + kb + c0 + 4];
                #pragma unroll
                for (int nt = 0; nt < 2; nt++) {
                    const int nb = nbase + nt * 8;
                    uint32_t b0 = Wt[(nb + r0) * FSP + kb + c0];
                    uint32_t b1 = Wt[(nb + r0) * FSP + kb + c0 + 4];
                    mma_tf32(c[nt], a0, a1, a2, a3, b0, b1);
                }
            }

            // store: C rows r0 (low) / r0+8 (high); pad rows skipped
            const int node = tile * TILE + r0;
            if (node < N) {
                float* o = out + (size_t)node * 128;
                #pragma unroll
                for (int nt = 0; nt < 2; nt++) {
                    int v0 = nbase + nt * 8 + 2 * c0;
                    if (m == 0) {            // scalar (low rows only)
                        o[v0]     = c[nt][0];
                        o[v0 + 1] = c[nt][1];
                    } else if (m == 1) {     // low = x, high = y
                        o[32 + 3 * v0 + 0]       = c[nt][0];
                        o[32 + 3 * (v0 + 1) + 0] = c[nt][1];
                        o[32 + 3 * v0 + 1]       = c[nt][2];
                        o[32 + 3 * (v0 + 1) + 1] = c[nt][3];
                    } else {                 // low = z (high rows are pad)
                        o[32 + 3 * v0 + 2]       = c[nt][0];
                        o[32 + 3 * (v0 + 1) + 2] = c[nt][1];
                    }
                }
            }
        }
    }
}

// ---------------------------------------------------------------------------
extern "C" void kernel_launch(void* const* d_in, const int* in_sizes, int n_in,
                              void* d_out, int out_size)
{
    const float* nf       = (const float*)d_in[0];
    const float* sh       = (const float*)d_in[1];
    const int*   senders  = (const int*)  d_in[2];
    const int*   recv     = (const int*)  d_in[3];
    const float* W0       = (const float*)d_in[4];
    const float* W1       = (const float*)d_in[5];
    const float* Ws0      = (const float*)d_in[6];
    const float* Ws1      = (const float*)d_in[7];
    float* out = (float*)d_out;

    int N = in_sizes[0] / 128;
    int E = in_sizes[2];

    k_fill<<<(E + 511) / 512, 512>>>(recv, senders, E);
    k_main<<<NBLK, 256>>>(nf, sh, W0, W1, Ws0, Ws1, out, N);
}